// round 14
// baseline (speedup 1.0000x reference)
#include <cuda_runtime.h>

typedef unsigned int u32;

#define REL_TOTAL  1000
#define BATCH      16384
#define MARGIN     4.0f
#define THREADS    384
#define GRID_MAIN  456     // 228 clusters of 2, 3 CTAs/SM

// ---- per-CTA smem byte offsets ----
#define OB_M     0         // bf16 M-half [200 e][104 j], stride 208B = 41600
#define OB_A     41600     // bf16 A [64][200] stride 400 (D-half overwrites, stride 208)
#define OB_R     67200     // f32 sR[200]
#define OB_NP4   68000     // f32 [64][3] quarter ssq partials
#define OB_NPL   68768     // f32 [64] local half ssq
#define OB_NPR   69024     // f32 [64] remote half ssq (peer writes)
#define OB_SCL   69280     // f32 [16][2] local score halves
#define OB_SCR   69408     // f32 [16][2] remote score halves (peer writes)
#define OB_XFER  69536     // int[770]: [0]=r, [1]=n, [2..257]=rows, [258..769]=perm
#define OB_CNT   72616
#define OB_RI    72620
#define OB_LAST  72624
#define MB_META  72632
#define MB_SSQ   72640
#define MB_SC    72648
#define SMEM_BYTES 72704

__device__ double g_part[REL_TOTAL];
__device__ int    g_done;
__device__ int    g_qhead;

__device__ __forceinline__ u32 smem_u32(const void* p) {
    u32 a;
    asm("{ .reg .u64 t; cvta.to.shared.u64 t, %1; cvt.u32.u64 %0, t; }" : "=r"(a) : "l"(p));
    return a;
}
__device__ __forceinline__ u32 ctarank() {
    u32 r; asm("mov.u32 %0, %%cluster_ctarank;" : "=r"(r)); return r;
}
__device__ __forceinline__ u32 mapa_peer(u32 addr, u32 peer) {
    u32 r; asm("mapa.shared::cluster.u32 %0, %1, %2;" : "=r"(r) : "r"(addr), "r"(peer));
    return r;
}
__device__ __forceinline__ void st_rem_u32(u32 a, u32 v) {
    asm volatile("st.shared::cluster.u32 [%0], %1;" :: "r"(a), "r"(v) : "memory");
}
__device__ __forceinline__ void st_rem_f32(u32 a, float v) {
    asm volatile("st.shared::cluster.f32 [%0], %1;" :: "r"(a), "f"(v) : "memory");
}
#define MBAR_INIT(mb, c)  asm volatile("mbarrier.init.shared.b64 [%0], %1;" :: "r"(mb), "r"(c) : "memory")
#define MBAR_ARR_LOC(mb)  asm volatile("mbarrier.arrive.shared.b64 _, [%0];" :: "r"(mb) : "memory")
#define MBAR_ARR_REM(mb)  asm volatile("mbarrier.arrive.shared::cluster.b64 _, [%0];" :: "r"(mb) : "memory")
#define CLUSTER_SYNC() do { \
    asm volatile("barrier.cluster.arrive.aligned;" ::: "memory"); \
    asm volatile("barrier.cluster.wait.aligned;" ::: "memory"); } while (0)

// cluster-scope acquire wait (synchronizes with peer's remote arrives/stores)
#define MBAR_WAIT_CL(mb, par) do {                                             \
    u32 _m = (mb), _p = (par), _d;                                             \
    asm volatile("{\n\t.reg .pred p;\n\t"                                      \
        "mbarrier.try_wait.parity.acquire.cluster.shared::cta.b64 p, [%1], %2;\n\t" \
        "selp.b32 %0, 1, 0, p;\n\t}" : "=r"(_d) : "r"(_m), "r"(_p) : "memory");\
    if (!_d) {                                                                 \
        asm volatile("{\n\t.reg .pred P1;\n\tW_%=:\n\t"                        \
            "mbarrier.try_wait.parity.acquire.cluster.shared::cta.b64 P1, [%0], %1, 0x989680;\n\t" \
            "@P1 bra.uni WD_%=;\n\tbra.uni W_%=;\n\tWD_%=:\n\t}"               \
            :: "r"(_m), "r"(_p) : "memory");                                   \
    }                                                                          \
} while (0)

__device__ __forceinline__ u32 bf2(float lo, float hi) {
    u32 d; asm("cvt.rn.bf16x2.f32 %0, %1, %2;" : "=r"(d) : "f"(hi), "f"(lo)); return d;
}
__device__ __forceinline__ float blo(u32 v) { return __uint_as_float(v << 16); }
__device__ __forceinline__ float bhi(u32 v) { return __uint_as_float(v & 0xffff0000u); }

__device__ __forceinline__ void ldsm4(u32& r0, u32& r1, u32& r2, u32& r3, u32 a) {
    asm volatile("ldmatrix.sync.aligned.m8n8.x4.shared.b16 {%0,%1,%2,%3}, [%4];"
                 : "=r"(r0), "=r"(r1), "=r"(r2), "=r"(r3) : "r"(a));
}
__device__ __forceinline__ void ldsm4t(u32& r0, u32& r1, u32& r2, u32& r3, u32 a) {
    asm volatile("ldmatrix.sync.aligned.m8n8.x4.trans.shared.b16 {%0,%1,%2,%3}, [%4];"
                 : "=r"(r0), "=r"(r1), "=r"(r2), "=r"(r3) : "r"(a));
}
__device__ __forceinline__ void ldsm2(u32& r0, u32& r1, u32 a) {
    asm volatile("ldmatrix.sync.aligned.m8n8.x2.shared.b16 {%0,%1}, [%2];"
                 : "=r"(r0), "=r"(r1) : "r"(a));
}
__device__ __forceinline__ void ldsm2t(u32& r0, u32& r1, u32 a) {
    asm volatile("ldmatrix.sync.aligned.m8n8.x2.trans.shared.b16 {%0,%1}, [%2];"
                 : "=r"(r0), "=r"(r1) : "r"(a));
}
__device__ __forceinline__ void mma16(float* c, u32 a0, u32 a1, u32 a2, u32 a3,
                                      u32 b0, u32 b1) {
    asm volatile(
        "mma.sync.aligned.m16n8k16.row.col.f32.bf16.bf16.f32 "
        "{%0,%1,%2,%3},{%4,%5,%6,%7},{%8,%9},{%0,%1,%2,%3};"
        : "+f"(c[0]), "+f"(c[1]), "+f"(c[2]), "+f"(c[3])
        : "r"(a0), "r"(a1), "r"(a2), "r"(a3), "r"(b0), "r"(b1));
}
__device__ __forceinline__ void mma8(float* c, u32 a0, u32 a1, u32 b0) {
    asm volatile(
        "mma.sync.aligned.m16n8k8.row.col.f32.bf16.bf16.f32 "
        "{%0,%1,%2,%3},{%4,%5},{%6},{%0,%1,%2,%3};"
        : "+f"(c[0]), "+f"(c[1]), "+f"(c[2]), "+f"(c[3])
        : "r"(a0), "r"(a1), "r"(b0));
}

__global__ void k_pre1() { if (threadIdx.x == 0) { g_done = 0; g_qhead = 0; } }

extern __shared__ char smc[];

__global__ void __launch_bounds__(THREADS, 3) __cluster_dims__(2, 1, 1)
k_main(const int* __restrict__ pos_h, const int* __restrict__ pos_t,
       const int* __restrict__ pos_r, const int* __restrict__ neg_h,
       const int* __restrict__ neg_t, const float* __restrict__ ent,
       const float* __restrict__ rel, const float* __restrict__ transfer,
       float* __restrict__ out)
{
    int*   sXfer = (int*)(smc + OB_XFER);
    int*   sRows = sXfer + 2;
    int*   sPerm = sXfer + 258;
    float* sR    = (float*)(smc + OB_R);
    float* sNP4  = (float*)(smc + OB_NP4);
    float* sNPL  = (float*)(smc + OB_NPL);
    float* sNPR  = (float*)(smc + OB_NPR);
    float* sSCL  = (float*)(smc + OB_SCL);
    float* sRi   = (float*)(smc + OB_RI);
    int*   sCnt  = (int*)(smc + OB_CNT);
    int*   sLast = (int*)(smc + OB_LAST);

    const u32 sb = smem_u32(smc);
    const u32 uM = sb + OB_M;
    const u32 uA = sb + OB_A;

    const int t    = threadIdx.x;
    const int lane = t & 31;
    const int warp = t >> 5;
    const u32 rank = ctarank();
    const u32 peer = rank ^ 1u;

    // remote addresses (peer's buffers)
    const u32 remNPR  = mapa_peer(sb + OB_NPR, peer);
    const u32 remSCR  = mapa_peer(sb + OB_SCR, peer);
    const u32 remXfer = mapa_peer(sb + OB_XFER, peer);
    const u32 remMeta = mapa_peer(sb + MB_META, peer);
    const u32 remSsq  = mapa_peer(sb + MB_SSQ, peer);
    const u32 remSc   = mapa_peer(sb + MB_SC, peer);

    if (t == 0) {
        MBAR_INIT(sb + MB_META, 32);
        MBAR_INIT(sb + MB_SSQ, 64);                     // 32 local + 32 remote lanes
        MBAR_INIT(sb + MB_SC, rank == 0 ? 24 : 1);      // 12 loc + 12 rem | 1 ack
    }
    __syncthreads();
    CLUSTER_SYNC();   // mbarriers visible cluster-wide

    // warp roles: rb = row block (16 rows of 64), q = col group over 13 tiles {5,4,4}
    const int rb    = warp & 3;
    const int rows0 = rb * 16;
    const int q     = warp >> 2;                 // 0..2
    const int nt0   = (q == 0) ? 0 : (q == 1 ? 5 : 9);
    const int ntN   = (q == 0) ? 5 : 4;

    const u32 aLd     = uA + (u32)(rows0 + (lane & 15)) * 400 + ((lane >> 4) << 4);
    const u32 aLdTail = uA + (u32)(rows0 + (lane & 15)) * 400 + 384;
    const u32 bLd     = uM + (u32)((((lane >> 3) & 1) << 3) + (lane & 7)) * 208
                           + ((lane >> 4) << 4) + nt0 * 16;
    const u32 bTail   = uM + (u32)(192 + (lane & 7)) * 208 + ((lane >> 3) << 4) + nt0 * 16;

    int meta_ph = 0, ssq_ph = 0, sc_ph = 0;
    int ack_ph = 0, ack_started = 0;
    double csum_rel = 0.0;   // only rank0 warp0 lane0 meaningful per relation

    for (;;) {
        __syncthreads();   // smem reusable

        // ================= meta phase =================
        if (rank == 0) {
            if (t == 0) { sXfer[0] = atomicAdd(&g_qhead, 1); *sCnt = 0; }
            __syncthreads();
            int r_ = sXfer[0];
            if (r_ < REL_TOTAL) {
                const int4* pr4 = (const int4*)pos_r;
                #pragma unroll 4
                for (int i = t; i < BATCH / 4; i += THREADS) {
                    int4 v = pr4[i];
                    if (v.x == r_) { int p = atomicAdd(sCnt, 1); if (p < 512) sPerm[p] = 4 * i; }
                    if (v.y == r_) { int p = atomicAdd(sCnt, 1); if (p < 512) sPerm[p] = 4 * i + 1; }
                    if (v.z == r_) { int p = atomicAdd(sCnt, 1); if (p < 512) sPerm[p] = 4 * i + 2; }
                    if (v.w == r_) { int p = atomicAdd(sCnt, 1); if (p < 512) sPerm[p] = 4 * i + 3; }
                }
                if (warp == 11) {
                    float ss = 0.f;
                    for (int j = lane; j < 200; j += 32) {
                        float v = rel[r_ * 200 + j];
                        sR[j] = v; ss += v * v;
                    }
                    #pragma unroll
                    for (int o = 16; o; o >>= 1) ss += __shfl_xor_sync(0xffffffffu, ss, o);
                    if (lane == 0) *sRi = rsqrtf(fmaxf(ss, 1e-12f));
                }
                __syncthreads();
                if (t == 0) sXfer[1] = *sCnt;
                __syncthreads();
                int nn = min(sXfer[1], 512);
                if (t < 256 && t < 4 * nn) {
                    int item = t >> 2, kind = t & 3;
                    int gi = sPerm[item];
                    sRows[t] = (kind == 0) ? pos_h[gi] : (kind == 1) ? pos_t[gi]
                             : (kind == 2) ? neg_h[gi] : neg_t[gi];
                }
                __syncthreads();
            }
            if (warp == 0) {   // ship r, n, rows, perm to rank1
                const u32* src = (const u32*)sXfer;
                for (int j = lane; j < 770; j += 32)
                    st_rem_u32(remXfer + 4u * j, src[j]);
                MBAR_ARR_REM(remMeta);   // 32 arrivals
            }
        } else {
            MBAR_WAIT_CL(sb + MB_META, meta_ph); meta_ph ^= 1;
            int r_ = sXfer[0];
            if (r_ < REL_TOTAL && warp == 11) {
                float ss = 0.f;
                for (int j = lane; j < 200; j += 32) {
                    float v = rel[r_ * 200 + j];
                    sR[j] = v; ss += v * v;
                }
                #pragma unroll
                for (int o = 16; o; o >>= 1) ss += __shfl_xor_sync(0xffffffffu, ss, o);
                if (lane == 0) *sRi = rsqrtf(fmaxf(ss, 1e-12f));
            }
        }
        const int r = sXfer[0];
        if (r >= REL_TOTAL) break;
        const int n = min(sXfer[1], 512);

        // ================= prologue: gather pass 0 + M-half load =================
        {
            int apairs0 = 4 * min(16, n);
            for (int pair = warp; pair < apairs0; pair += 12) {
                const float4* src = (const float4*)(ent + (size_t)sRows[pair] * 200);
                uint2* dst = (uint2*)(smc + OB_A + pair * 400);
                float4 v0 = src[lane];
                dst[lane] = make_uint2(bf2(v0.x, v0.y), bf2(v0.z, v0.w));
                if (lane < 18) {
                    float4 v1 = src[lane + 32];
                    dst[lane + 32] = make_uint2(bf2(v1.x, v1.y), bf2(v1.z, v1.w));
                }
            }
            const float* Msrc = transfer + (size_t)r * 40000 + rank * 100;
            #pragma unroll 4
            for (int i = t; i < 5000; i += THREADS) {
                int e = i / 25, jl = i % 25;
                float4 v = __ldg((const float4*)(Msrc + e * 200) + jl);
                *(uint2*)(smc + OB_M + e * 208 + jl * 8) =
                    make_uint2(bf2(v.x, v.y), bf2(v.z, v.w));
            }
            for (int i = t; i < 200; i += THREADS)   // zero pad cols 100..103
                *(uint2*)(smc + OB_M + i * 208 + 200) = make_uint2(0u, 0u);
        }
        __syncthreads();

        const float  ri = *sRi;
        const float2* r2 = (const float2*)sR;
        double csum = 0.0;

        // ================= pass loop =================
        for (int ib = 0; ib < n; ib += 16) {
            const int cnt    = min(16, n - ib);
            const int apairs = 4 * cnt;

            // ---- mma: D-half[64][104] = A[64][200] * M-half ----
            float acc[5][4];
            const bool active = rows0 < apairs;
            if (active) {
                #pragma unroll
                for (int nt = 0; nt < 5; nt++)
                    acc[nt][0] = acc[nt][1] = acc[nt][2] = acc[nt][3] = 0.f;
                #pragma unroll 2
                for (int kt = 0; kt < 12; kt++) {
                    u32 A0, A1, A2, A3;
                    ldsm4(A0, A1, A2, A3, aLd + kt * 32);
                    u32 bk = bLd + kt * 3328;
                    u32 B0, B1, B2, B3;
                    ldsm4t(B0, B1, B2, B3, bk);
                    mma16(acc[0], A0, A1, A2, A3, B0, B1);
                    mma16(acc[1], A0, A1, A2, A3, B2, B3);
                    ldsm4t(B0, B1, B2, B3, bk + 32);
                    mma16(acc[2], A0, A1, A2, A3, B0, B1);
                    mma16(acc[3], A0, A1, A2, A3, B2, B3);
                    if (ntN == 5) {
                        ldsm2t(B0, B1, bk + 64);
                        mma16(acc[4], A0, A1, A2, A3, B0, B1);
                    }
                }
                {   // tail k = 192..199
                    u32 A0, A1;
                    ldsm2(A0, A1, aLdTail);
                    u32 B0, B1, B2, B3;
                    ldsm4t(B0, B1, B2, B3, bTail);
                    mma8(acc[0], A0, A1, B0);
                    mma8(acc[1], A0, A1, B1);
                    mma8(acc[2], A0, A1, B2);
                    mma8(acc[3], A0, A1, B3);
                    if (ntN == 5) {
                        ldsm2t(B0, B1, bTail + 64);
                        mma8(acc[4], A0, A1, B0);
                    }
                }
            }
            __syncthreads();   // A reads done; region becomes D-half (stride 208)

            if (active) {
                const int rg = lane >> 2, tig = lane & 3;
                float s0 = 0.f, s1 = 0.f;
                #pragma unroll
                for (int nt = 0; nt < 5; nt++) {
                    if (nt >= ntN) break;
                    s0 += acc[nt][0] * acc[nt][0] + acc[nt][1] * acc[nt][1];
                    s1 += acc[nt][2] * acc[nt][2] + acc[nt][3] * acc[nt][3];
                    int colB = ((nt0 + nt) * 8 + 2 * tig) * 2;
                    char* d0 = smc + OB_A + (rows0 + rg) * 208 + colB;
                    *(u32*)d0 = bf2(acc[nt][0], acc[nt][1]);
                    *(u32*)(d0 + 8 * 208) = bf2(acc[nt][2], acc[nt][3]);
                }
                s0 += __shfl_xor_sync(0xffffffffu, s0, 1);
                s0 += __shfl_xor_sync(0xffffffffu, s0, 2);
                s1 += __shfl_xor_sync(0xffffffffu, s1, 1);
                s1 += __shfl_xor_sync(0xffffffffu, s1, 2);
                if (tig == 0) {
                    sNP4[(rows0 + rg) * 3 + q] = s0;
                    sNP4[(rows0 + rg + 8) * 3 + q] = s1;
                }
            }
            __syncthreads();

            // ---- ssq exchange (warp 0): local NPL + remote NPR ----
            if (warp == 0) {
                if (rank == 1) {   // backpressure: rank0 consumed previous NPR
                    if (ack_started) { MBAR_WAIT_CL(sb + MB_SC, ack_ph); ack_ph ^= 1; }
                    ack_started = 1;
                }
                #pragma unroll
                for (int h = 0; h < 2; h++) {
                    int row = lane + 32 * h;
                    float v = sNP4[row * 3] + sNP4[row * 3 + 1] + sNP4[row * 3 + 2];
                    sNPL[row] = v;
                    st_rem_f32(remNPR + 4u * row, v);
                }
                MBAR_ARR_LOC(sb + MB_SSQ);
                MBAR_ARR_REM(remSsq);
            }
            MBAR_WAIT_CL(sb + MB_SSQ, ssq_ph); ssq_ph ^= 1;

            // ---- scores (half, over this CTA's 100 cols) ----
            for (int itm = warp; itm < cnt; itm += 12) {
                int lr = 4 * itm;
                float ihp  = rsqrtf(fmaxf(sNPL[lr]     + sNPR[lr],     1e-12f));
                float itp  = rsqrtf(fmaxf(sNPL[lr + 1] + sNPR[lr + 1], 1e-12f));
                float inh  = rsqrtf(fmaxf(sNPL[lr + 2] + sNPR[lr + 2], 1e-12f));
                float int_ = rsqrtf(fmaxf(sNPL[lr + 3] + sNPR[lr + 3], 1e-12f));
                const u32* vph = (const u32*)(smc + OB_A + (lr    ) * 208);
                const u32* vpt = (const u32*)(smc + OB_A + (lr + 1) * 208);
                const u32* vnh = (const u32*)(smc + OB_A + (lr + 2) * 208);
                const u32* vnt = (const u32*)(smc + OB_A + (lr + 3) * 208);
                float scp = 0.f, scn = 0.f;
                #pragma unroll
                for (int ii = 0; ii < 2; ii++) {
                    int w = lane + 32 * ii;
                    if (w < 50) {
                        float2 rr = r2[rank * 50 + w];
                        float rx = rr.x * ri, ry = rr.y * ri;
                        u32 a = vph[w], b = vpt[w];
                        scp += fabsf(blo(a) * ihp + rx - blo(b) * itp)
                             + fabsf(bhi(a) * ihp + ry - bhi(b) * itp);
                        u32 c = vnh[w], d = vnt[w];
                        scn += fabsf(blo(c) * inh + rx - blo(d) * int_)
                             + fabsf(bhi(c) * inh + ry - bhi(d) * int_);
                    }
                }
                #pragma unroll
                for (int o = 16; o; o >>= 1) {
                    scp += __shfl_xor_sync(0xffffffffu, scp, o);
                    scn += __shfl_xor_sync(0xffffffffu, scn, o);
                }
                if (lane == 0) {
                    if (rank == 0) {
                        sSCL[2 * itm] = scp; sSCL[2 * itm + 1] = scn;
                    } else {
                        st_rem_f32(remSCR + 4u * (2 * itm), scp);
                        st_rem_f32(remSCR + 4u * (2 * itm + 1), scn);
                    }
                }
            }
            if (lane == 0) {   // every warp arrives once (uniform count)
                if (rank == 0) MBAR_ARR_LOC(sb + MB_SC);
                else           MBAR_ARR_REM(remSc);
            }

            // ---- rank0 warp0: combine halves, hinge, ack ----
            if (rank == 0 && warp == 0) {
                MBAR_WAIT_CL(sb + MB_SC, sc_ph);
                const float* SCL = sSCL;
                const float* SCR = (const float*)(smc + OB_SCR);
                double v = 0.0;
                if (lane < cnt) {
                    float p = SCL[2 * lane] + SCR[2 * lane];
                    float ng = SCL[2 * lane + 1] + SCR[2 * lane + 1];
                    float dl = p - ng + MARGIN;
                    if (dl > 0.f) v = (double)dl;
                }
                #pragma unroll
                for (int o = 16; o; o >>= 1) v += __shfl_down_sync(0xffffffffu, v, o);
                if (lane == 0) {
                    csum += v;
                    MBAR_ARR_REM(remSc);   // ack to rank1 (count 1)
                }
            }
            sc_ph ^= 1;
            __syncthreads();   // all local D reads done

            // ---- prefetch next pass's gather ----
            if (ib + 16 < n) {
                int ap2 = 4 * min(16, n - ib - 16);
                int gb  = 4 * (ib + 16);
                for (int pair = warp; pair < ap2; pair += 12) {
                    int gp = gb + pair;
                    int row;
                    if (gp < 256) {
                        row = sRows[gp];
                    } else {
                        int gi = sPerm[gp >> 2];
                        int kind = gp & 3;
                        row = (kind == 0) ? pos_h[gi] : (kind == 1) ? pos_t[gi]
                            : (kind == 2) ? neg_h[gi] : neg_t[gi];
                    }
                    const float4* src = (const float4*)(ent + (size_t)row * 200);
                    uint2* dst = (uint2*)(smc + OB_A + pair * 400);
                    float4 v0 = src[lane];
                    dst[lane] = make_uint2(bf2(v0.x, v0.y), bf2(v0.z, v0.w));
                    if (lane < 18) {
                        float4 v1 = src[lane + 32];
                        dst[lane + 32] = make_uint2(bf2(v1.x, v1.y), bf2(v1.z, v1.w));
                    }
                }
            }
            __syncthreads();
        }

        if (rank == 0 && warp == 0 && lane == 0) {
            g_part[r] = csum;
            csum_rel = 0.0; (void)csum_rel;
        }
    }

    CLUSTER_SYNC();   // no in-flight remote ops past here

    if (t == 0) {
        __threadfence();
        int d = atomicAdd(&g_done, 1);
        *sLast = (d == GRID_MAIN - 1) ? 1 : 0;
    }
    __syncthreads();
    if (*sLast) {
        double* s = (double*)smc;   // reuse M region
        if (t < 128) {
            double v = 0.0;
            for (int k = t; k < REL_TOTAL; k += 128) v += g_part[k];
            s[t] = v;
        }
        __syncthreads();
        for (int o = 64; o; o >>= 1) {
            if (t < o) s[t] += s[t + o];
            __syncthreads();
        }
        if (t == 0) out[0] = (float)(s[0] / (double)BATCH);
    }
}

extern "C" void kernel_launch(void* const* d_in, const int* in_sizes, int n_in,
                              void* d_out, int out_size) {
    const int*   pos_h    = (const int*)d_in[0];
    const int*   pos_t    = (const int*)d_in[1];
    const int*   pos_r    = (const int*)d_in[2];
    const int*   neg_h    = (const int*)d_in[3];
    const int*   neg_t    = (const int*)d_in[4];
    const float* ent      = (const float*)d_in[5];
    const float* rel      = (const float*)d_in[6];
    const float* transfer = (const float*)d_in[7];
    float* out = (float*)d_out;

    cudaFuncSetAttribute(k_main, cudaFuncAttributeMaxDynamicSharedMemorySize, SMEM_BYTES);

    k_pre1<<<1, 32>>>();
    k_main<<<GRID_MAIN, THREADS, SMEM_BYTES>>>(pos_h, pos_t, pos_r, neg_h, neg_t,
                                               ent, rel, transfer, out);
}

// round 15
// speedup vs baseline: 1.4395x; 1.4395x over previous
#include <cuda_runtime.h>

typedef unsigned int u32;

#define REL_TOTAL  1000
#define BATCH      16384
#define MARGIN     4.0f
#define THREADS    512
#define GRID_MAIN  304

// ---- smem byte offsets ----
#define OB_M     0        // bf16 [200][200], row stride 400B
#define OB_A     80000    // bf16 [64][200], row stride 400B (A/D; reduce buf at end)
#define OB_R     105600   // f32[200]
#define OB_NP    106400   // f32 sNpart[64][4]
#define OB_CS    107424   // double csumW[16]
#define OB_RI    107552   // f32 (+pad)
#define OB_ROWS  107568   // int[256]
#define OB_CNT   108592   // int (unused slack below)
#define OB_REL   108596   // int
#define OB_LAST  108600   // int
#define SMEM_BYTES 108608

__device__ double g_part[REL_TOTAL];
__device__ int    g_done;
__device__ int    g_qhead;
__device__ int    g_cnt[REL_TOTAL];            // zero-init; re-zeroed by last CTA
__device__ int    g_permG[REL_TOTAL * 512];

__device__ __forceinline__ u32 smem_u32(const void* p) {
    u32 a;
    asm("{ .reg .u64 t; cvta.to.shared.u64 t, %1; cvt.u32.u64 %0, t; }" : "=r"(a) : "l"(p));
    return a;
}
__device__ __forceinline__ u32 bf2(float lo, float hi) {
    u32 d; asm("cvt.rn.bf16x2.f32 %0, %1, %2;" : "=r"(d) : "f"(hi), "f"(lo)); return d;
}
__device__ __forceinline__ float blo(u32 v) { return __uint_as_float(v << 16); }
__device__ __forceinline__ float bhi(u32 v) { return __uint_as_float(v & 0xffff0000u); }

__device__ __forceinline__ void ldsm4(u32& r0, u32& r1, u32& r2, u32& r3, u32 a) {
    asm volatile("ldmatrix.sync.aligned.m8n8.x4.shared.b16 {%0,%1,%2,%3}, [%4];"
                 : "=r"(r0), "=r"(r1), "=r"(r2), "=r"(r3) : "r"(a));
}
__device__ __forceinline__ void ldsm4t(u32& r0, u32& r1, u32& r2, u32& r3, u32 a) {
    asm volatile("ldmatrix.sync.aligned.m8n8.x4.trans.shared.b16 {%0,%1,%2,%3}, [%4];"
                 : "=r"(r0), "=r"(r1), "=r"(r2), "=r"(r3) : "r"(a));
}
__device__ __forceinline__ void ldsm2(u32& r0, u32& r1, u32 a) {
    asm volatile("ldmatrix.sync.aligned.m8n8.x2.shared.b16 {%0,%1}, [%2];"
                 : "=r"(r0), "=r"(r1) : "r"(a));
}
__device__ __forceinline__ void ldsm2t(u32& r0, u32& r1, u32 a) {
    asm volatile("ldmatrix.sync.aligned.m8n8.x2.trans.shared.b16 {%0,%1}, [%2];"
                 : "=r"(r0), "=r"(r1) : "r"(a));
}
__device__ __forceinline__ void mma16(float* c, u32 a0, u32 a1, u32 a2, u32 a3,
                                      u32 b0, u32 b1) {
    asm volatile(
        "mma.sync.aligned.m16n8k16.row.col.f32.bf16.bf16.f32 "
        "{%0,%1,%2,%3},{%4,%5,%6,%7},{%8,%9},{%0,%1,%2,%3};"
        : "+f"(c[0]), "+f"(c[1]), "+f"(c[2]), "+f"(c[3])
        : "r"(a0), "r"(a1), "r"(a2), "r"(a3), "r"(b0), "r"(b1));
}
__device__ __forceinline__ void mma8(float* c, u32 a0, u32 a1, u32 b0) {
    asm volatile(
        "mma.sync.aligned.m16n8k8.row.col.f32.bf16.bf16.f32 "
        "{%0,%1,%2,%3},{%4,%5},{%6},{%0,%1,%2,%3};"
        : "+f"(c[0]), "+f"(c[1]), "+f"(c[2]), "+f"(c[3])
        : "r"(a0), "r"(a1), "r"(b0));
}

// ---- prep: build per-relation item lists via global atomics ----
__global__ void k_prep(const int* __restrict__ pos_r) {
    int i = blockIdx.x * blockDim.x + threadIdx.x;
    int stride = gridDim.x * blockDim.x;
    for (; i < BATCH; i += stride) {
        int r = pos_r[i];
        int p = atomicAdd(&g_cnt[r], 1);
        if (p < 512) g_permG[r * 512 + p] = i;
    }
}

extern __shared__ char smc[];

__global__ void __launch_bounds__(THREADS, 2)
k_main(const int* __restrict__ pos_h, const int* __restrict__ pos_t,
       const int* __restrict__ pos_r, const int* __restrict__ neg_h,
       const int* __restrict__ neg_t, const float* __restrict__ ent,
       const float* __restrict__ rel, const float* __restrict__ transfer,
       float* __restrict__ out)
{
    float*  sR    = (float*)(smc + OB_R);
    float*  sNP   = (float*)(smc + OB_NP);
    double* sCS   = (double*)(smc + OB_CS);
    float*  sRi   = (float*)(smc + OB_RI);
    int*    sRows = (int*)(smc + OB_ROWS);
    int*    sRel  = (int*)(smc + OB_REL);
    int*    sLast = (int*)(smc + OB_LAST);

    const u32 sb = smem_u32(smc);
    const u32 uM = sb + OB_M;
    const u32 uA = sb + OB_A;

    const int t    = threadIdx.x;
    const int lane = t & 31;
    const int warp = t >> 5;

    const int grp  = warp >> 3;
    const int wl   = warp & 7;
    const int bid  = 1 + grp;
    const int rb   = wl & 1;
    const int q    = wl >> 1;
    const int rows0 = grp * 32 + rb * 16;
    const int nt0  = q ? (1 + 6 * q) : 0;
    const int ntN  = q ? 6 : 7;

    const u32 aLd     = uA + (u32)(rows0 + (lane & 15)) * 400 + ((lane >> 4) << 4);
    const u32 aLdTail = uA + (u32)(rows0 + (lane & 15)) * 400 + 384;
    const u32 bLd     = uM + (u32)((((lane >> 3) & 1) << 3) + (lane & 7)) * 400
                           + ((lane >> 4) << 4) + nt0 * 16;
    const u32 bTail   = uM + (u32)(192 + (lane & 7)) * 400 + ((lane >> 3) << 4) + nt0 * 16;

    #define BARG(id) asm volatile("bar.sync %0, 256;" :: "r"(id) : "memory")

    // ---- persistent relation loop ----
    for (;;) {
        __syncthreads();
        if (t == 0) *sRel = atomicAdd(&g_qhead, 1);
        __syncthreads();
        const int r = *sRel;
        if (r >= REL_TOTAL) break;

        const int n = min(g_cnt[r], 512);
        const int* permR = g_permG + r * 512;

        // rel embedding + inverse norm
        if (warp == 15) {
            float ss = 0.f;
            for (int j = lane; j < 200; j += 32) {
                float v = rel[r * 200 + j];
                sR[j] = v; ss += v * v;
            }
            #pragma unroll
            for (int o = 16; o; o >>= 1) ss += __shfl_xor_sync(0xffffffffu, ss, o);
            if (lane == 0) *sRi = rsqrtf(fmaxf(ss, 1e-12f));
        }
        // pre-resolve row indices for global pairs 0..255
        if (t < 256 && t < 4 * n) {
            int gi = permR[t >> 2];
            int kind = t & 3;
            sRows[t] = (kind == 0) ? pos_h[gi] : (kind == 1) ? pos_t[gi]
                     : (kind == 2) ? neg_h[gi] : neg_t[gi];
        }
        __syncthreads();

        // gather pass 0 (hides under M load)
        {
            int ap0 = 4 * min(16, n);
            #pragma unroll
            for (int i = 0; i < 4; i++) {
                int pair = warp + 16 * i;
                if (pair < ap0) {
                    const float4* src = (const float4*)(ent + (size_t)sRows[pair] * 200);
                    uint2* dst = (uint2*)(smc + OB_A + pair * 400);
                    float4 v0 = src[lane];
                    dst[lane] = make_uint2(bf2(v0.x, v0.y), bf2(v0.z, v0.w));
                    if (lane < 18) {
                        float4 v1 = src[lane + 32];
                        dst[lane + 32] = make_uint2(bf2(v1.x, v1.y), bf2(v1.z, v1.w));
                    }
                }
            }
        }

        // M load: register-batched (3 batches of 7 LDG.128)
        {
            const float4* src = (const float4*)(transfer + (size_t)r * 40000);
            uint2* dst = (uint2*)(smc + OB_M);
            float4 v[7];
            #pragma unroll
            for (int k = 0; k < 7; k++) v[k] = src[t + 512 * k];
            #pragma unroll
            for (int k = 0; k < 7; k++)
                dst[t + 512 * k] = make_uint2(bf2(v[k].x, v[k].y), bf2(v[k].z, v[k].w));
            #pragma unroll
            for (int k = 0; k < 7; k++) v[k] = src[t + 512 * (7 + k)];
            #pragma unroll
            for (int k = 0; k < 7; k++)
                dst[t + 512 * (7 + k)] = make_uint2(bf2(v[k].x, v[k].y), bf2(v[k].z, v[k].w));
            #pragma unroll
            for (int k = 0; k < 5; k++) v[k] = src[t + 512 * (14 + k)];
            bool tail = t < 272;
            if (tail) v[5] = src[t + 512 * 19];
            #pragma unroll
            for (int k = 0; k < 5; k++)
                dst[t + 512 * (14 + k)] = make_uint2(bf2(v[k].x, v[k].y), bf2(v[k].z, v[k].w));
            if (tail)
                dst[t + 512 * 19] = make_uint2(bf2(v[5].x, v[5].y), bf2(v[5].z, v[5].w));
        }
        __syncthreads();

        const float  ri = *sRi;
        const float2* r2 = (const float2*)sR;
        double csum = 0.0;

        // ---- per-group pass loop: group g handles items p*16 + 8g + wl ----
        for (int ib = grp * 8; ib < n; ib += 16) {
            const int cg = min(8, n - ib);

            float acc[7][4];
            const bool active = rb * 16 < 4 * cg;
            if (active) {
                #pragma unroll
                for (int nt = 0; nt < 7; nt++)
                    acc[nt][0] = acc[nt][1] = acc[nt][2] = acc[nt][3] = 0.f;

                #pragma unroll 2
                for (int kt = 0; kt < 12; kt++) {
                    u32 A0, A1, A2, A3;
                    ldsm4(A0, A1, A2, A3, aLd + kt * 32);
                    u32 bk = bLd + kt * 6400;
                    u32 B0, B1, B2, B3;
                    ldsm4t(B0, B1, B2, B3, bk);
                    mma16(acc[0], A0, A1, A2, A3, B0, B1);
                    mma16(acc[1], A0, A1, A2, A3, B2, B3);
                    ldsm4t(B0, B1, B2, B3, bk + 32);
                    mma16(acc[2], A0, A1, A2, A3, B0, B1);
                    mma16(acc[3], A0, A1, A2, A3, B2, B3);
                    ldsm4t(B0, B1, B2, B3, bk + 64);
                    mma16(acc[4], A0, A1, A2, A3, B0, B1);
                    mma16(acc[5], A0, A1, A2, A3, B2, B3);
                    if (ntN == 7) {
                        ldsm2t(B0, B1, bk + 96);
                        mma16(acc[6], A0, A1, A2, A3, B0, B1);
                    }
                }
                {   // tail k = 192..199
                    u32 A0, A1;
                    ldsm2(A0, A1, aLdTail);
                    u32 B0, B1, B2, B3;
                    ldsm4t(B0, B1, B2, B3, bTail);
                    mma8(acc[0], A0, A1, B0);
                    mma8(acc[1], A0, A1, B1);
                    mma8(acc[2], A0, A1, B2);
                    mma8(acc[3], A0, A1, B3);
                    if (ntN == 7) {
                        ldsm4t(B0, B1, B2, B3, bTail + 48);
                        mma8(acc[4], A0, A1, B1);
                        mma8(acc[5], A0, A1, B2);
                        mma8(acc[6], A0, A1, B3);
                    } else {
                        ldsm2t(B0, B1, bTail + 64);
                        mma8(acc[4], A0, A1, B0);
                        mma8(acc[5], A0, A1, B1);
                    }
                }
            }
            BARG(bid);

            if (active) {
                const int rg = lane >> 2, tig = lane & 3;
                float s0 = 0.f, s1 = 0.f;
                #pragma unroll
                for (int nt = 0; nt < 7; nt++) {
                    if (nt >= ntN) break;
                    s0 += acc[nt][0] * acc[nt][0] + acc[nt][1] * acc[nt][1];
                    s1 += acc[nt][2] * acc[nt][2] + acc[nt][3] * acc[nt][3];
                    int colB = ((nt0 + nt) * 8 + 2 * tig) * 2;
                    char* d0 = smc + OB_A + (rows0 + rg) * 400 + colB;
                    *(u32*)d0 = bf2(acc[nt][0], acc[nt][1]);
                    *(u32*)(d0 + 8 * 400) = bf2(acc[nt][2], acc[nt][3]);
                }
                s0 += __shfl_xor_sync(0xffffffffu, s0, 1);
                s0 += __shfl_xor_sync(0xffffffffu, s0, 2);
                s1 += __shfl_xor_sync(0xffffffffu, s1, 1);
                s1 += __shfl_xor_sync(0xffffffffu, s1, 2);
                if (tig == 0) {
                    sNP[(rows0 + rg) * 4 + q] = s0;
                    sNP[(rows0 + rg + 8) * 4 + q] = s1;
                }
            }
            BARG(bid);

            if (wl < cg) {
                int lr = grp * 32 + 4 * wl;
                const float* p0 = sNP + lr * 4;
                float ihp = rsqrtf(fmaxf(p0[0] + p0[1] + p0[2] + p0[3], 1e-12f));
                float itp = rsqrtf(fmaxf(p0[4] + p0[5] + p0[6] + p0[7], 1e-12f));
                float inh = rsqrtf(fmaxf(p0[8] + p0[9] + p0[10] + p0[11], 1e-12f));
                float int_ = rsqrtf(fmaxf(p0[12] + p0[13] + p0[14] + p0[15], 1e-12f));
                const u32* vph = (const u32*)(smc + OB_A + (lr    ) * 400);
                const u32* vpt = (const u32*)(smc + OB_A + (lr + 1) * 400);
                const u32* vnh = (const u32*)(smc + OB_A + (lr + 2) * 400);
                const u32* vnt = (const u32*)(smc + OB_A + (lr + 3) * 400);
                float scp = 0.f, scn = 0.f;
                #pragma unroll
                for (int ii = 0; ii < 4; ii++) {
                    int w = lane + 32 * ii;
                    if (w < 100) {
                        float2 rr = r2[w];
                        float rx = rr.x * ri, ry = rr.y * ri;
                        u32 a = vph[w], b = vpt[w];
                        scp += fabsf(blo(a) * ihp + rx - blo(b) * itp)
                             + fabsf(bhi(a) * ihp + ry - bhi(b) * itp);
                        u32 c = vnh[w], d = vnt[w];
                        scn += fabsf(blo(c) * inh + rx - blo(d) * int_)
                             + fabsf(bhi(c) * inh + ry - bhi(d) * int_);
                    }
                }
                #pragma unroll
                for (int o = 16; o; o >>= 1) {
                    scp += __shfl_xor_sync(0xffffffffu, scp, o);
                    scn += __shfl_xor_sync(0xffffffffu, scn, o);
                }
                float dl = scp - scn + MARGIN;
                if (lane == 0 && dl > 0.f) csum += (double)dl;
            }
            BARG(bid);

            {   // prefetch next pass's items for this group
                int ibn = ib + 16;
                if (ibn < n && ibn + wl < n) {
                    #pragma unroll
                    for (int i = 0; i < 4; i++) {
                        int gp = 4 * (ibn + wl) + i;
                        int row;
                        if (gp < 256) {
                            row = sRows[gp];
                        } else {
                            int gi = permR[gp >> 2];
                            int kind = gp & 3;
                            row = (kind == 0) ? pos_h[gi] : (kind == 1) ? pos_t[gi]
                                : (kind == 2) ? neg_h[gi] : neg_t[gi];
                        }
                        const float4* src = (const float4*)(ent + (size_t)row * 200);
                        uint2* dst = (uint2*)(smc + OB_A + (grp * 32 + 4 * wl + i) * 400);
                        float4 v0 = src[lane];
                        dst[lane] = make_uint2(bf2(v0.x, v0.y), bf2(v0.z, v0.w));
                        if (lane < 18) {
                            float4 v1 = src[lane + 32];
                            dst[lane + 32] = make_uint2(bf2(v1.x, v1.y), bf2(v1.z, v1.w));
                        }
                    }
                }
            }
            if (ib + 16 < n) BARG(bid);
        }

        // deterministic per-relation aggregation
        if (lane == 0) sCS[warp] = csum;
        __syncthreads();
        if (t == 0) {
            double s = 0.0;
            #pragma unroll
            for (int w = 0; w < 16; w++) s += sCS[w];
            g_part[r] = s;
        }
    }

    // ---- last CTA out: final reduction + counter reset for graph replay ----
    if (t == 0) {
        __threadfence();
        int d = atomicAdd(&g_done, 1);
        *sLast = (d == GRID_MAIN - 1) ? 1 : 0;
    }
    __syncthreads();
    if (*sLast) {
        double* s = (double*)(smc + OB_A);
        double v = 0.0;
        if (t < 500) v = g_part[t] + g_part[t + 500];
        s[t] = v;
        // reset global counters for the next graph replay
        for (int i = t; i < REL_TOTAL; i += THREADS) g_cnt[i] = 0;
        if (t == 0) { g_qhead = 0; g_done = 0; }
        __syncthreads();
        #pragma unroll
        for (int o = 256; o; o >>= 1) {
            if (t < o) s[t] += s[t + o];
            __syncthreads();
        }
        if (t == 0) out[0] = (float)(s[0] / (double)BATCH);
    }
}

extern "C" void kernel_launch(void* const* d_in, const int* in_sizes, int n_in,
                              void* d_out, int out_size) {
    const int*   pos_h    = (const int*)d_in[0];
    const int*   pos_t    = (const int*)d_in[1];
    const int*   pos_r    = (const int*)d_in[2];
    const int*   neg_h    = (const int*)d_in[3];
    const int*   neg_t    = (const int*)d_in[4];
    const float* ent      = (const float*)d_in[5];
    const float* rel      = (const float*)d_in[6];
    const float* transfer = (const float*)d_in[7];
    float* out = (float*)d_out;

    cudaFuncSetAttribute(k_main, cudaFuncAttributeMaxDynamicSharedMemorySize, SMEM_BYTES);

    k_prep<<<64, 256>>>(pos_r);
    k_main<<<GRID_MAIN, THREADS, SMEM_BYTES>>>(pos_h, pos_t, pos_r, neg_h, neg_t,
                                               ent, rel, transfer, out);
}